// round 3
// baseline (speedup 1.0000x reference)
#include <cuda_runtime.h>
#include <math.h>
#include <stdint.h>

#define N_NODES 50000
#define D2      512
#define HEADS   4
#define CH      128
#define NEG     0.2f
#define MAXE    450048   // 400000 edges + 50000 self loops, padded

// ---------------- scratch (static device globals; no runtime alloc) -------
__device__ __align__(128) float g_bufA[(size_t)N_NODES * D2];
__device__ __align__(128) float g_bufB[(size_t)N_NODES * D2];
__device__ __align__(128) float g_xl  [(size_t)N_NODES * D2];
__device__ __align__(128) float g_xr  [(size_t)N_NODES * D2];
__device__ __align__(128) float g_p   [(size_t)MAXE * HEADS];
__device__ __align__(128) float g_den [(size_t)N_NODES * HEADS];

// ---------------- fp32 tiled SGEMM: C[M,N] = A[M,K] @ B[K,N] (+bias) ------
// 128x128 tile, BK=16, 256 threads, 8x8 per thread.
__global__ void __launch_bounds__(256)
sgemm_kernel(const float* __restrict__ A, const float* __restrict__ B,
             float* __restrict__ C, int M, int N, int K,
             const float* __restrict__ bias)
{
    __shared__ float As[16][128];
    __shared__ float Bs[16][128];

    const int tid  = threadIdx.x;
    const int tx   = tid & 15;
    const int ty   = tid >> 4;
    const int row0 = blockIdx.y * 128;
    const int col0 = blockIdx.x * 128;

    float acc[8][8];
#pragma unroll
    for (int i = 0; i < 8; i++)
#pragma unroll
        for (int j = 0; j < 8; j++) acc[i][j] = 0.f;

    const int a_r = tid >> 1;          // 0..127
    const int a_c = (tid & 1) * 8;     // 0 or 8
    const int b_r = tid >> 5;          // 0..7
    const int b_c = (tid & 31) * 4;    // 0..124

    for (int k0 = 0; k0 < K; k0 += 16) {
        // A tile (transposed into As[k][m])
#pragma unroll
        for (int i = 0; i < 8; i++) {
            int kk = k0 + a_c + i;
            float v = 0.f;
            if (row0 + a_r < M && kk < K)
                v = A[(size_t)(row0 + a_r) * K + kk];
            As[a_c + i][a_r] = v;
        }
        // B tile
#pragma unroll
        for (int i = 0; i < 2; i++) {
            int kk = k0 + b_r + i * 8;
#pragma unroll
            for (int j = 0; j < 4; j++) {
                int cc = col0 + b_c + j;
                float v = 0.f;
                if (kk < K && cc < N)
                    v = B[(size_t)kk * N + cc];
                Bs[b_r + i * 8][b_c + j] = v;
            }
        }
        __syncthreads();

#pragma unroll
        for (int kk = 0; kk < 16; kk++) {
            float a[8], b[8];
#pragma unroll
            for (int i = 0; i < 4; i++) {
                a[i]     = As[kk][ty * 4 + i];
                a[4 + i] = As[kk][64 + ty * 4 + i];
            }
#pragma unroll
            for (int j = 0; j < 4; j++) {
                b[j]     = Bs[kk][tx * 4 + j];
                b[4 + j] = Bs[kk][64 + tx * 4 + j];
            }
#pragma unroll
            for (int i = 0; i < 8; i++)
#pragma unroll
                for (int j = 0; j < 8; j++)
                    acc[i][j] = fmaf(a[i], b[j], acc[i][j]);
        }
        __syncthreads();
    }

#pragma unroll
    for (int i = 0; i < 8; i++) {
        int r = row0 + ((i < 4) ? (ty * 4 + i) : (64 + ty * 4 + (i - 4)));
        if (r >= M) continue;
#pragma unroll
        for (int j = 0; j < 8; j++) {
            int c = col0 + ((j < 4) ? (tx * 4 + j) : (64 + tx * 4 + (j - 4)));
            if (c < N)
                C[(size_t)r * N + c] = acc[i][j] + (bias ? bias[c] : 0.f);
        }
    }
}

// ---------------- edge pass A: logits -> p = exp(logit), denom += p -------
// One warp per edge (edges >= E are implicit self loops).
// Softmax is shift-invariant: skipping the segment-max pass is exact as long
// as exp() doesn't overflow; logits here are O(1).
__global__ void edge_logits_kernel(const float* __restrict__ xl,
                                   const float* __restrict__ xr,
                                   const int* __restrict__ ei,
                                   int E, int ET,
                                   const float* __restrict__ att,
                                   float* __restrict__ p,
                                   float* __restrict__ denom)
{
    int warp = (blockIdx.x * blockDim.x + threadIdx.x) >> 5;
    int lane = threadIdx.x & 31;
    if (warp >= ET) return;

    int src, dst;
    if (warp < E) { src = ei[warp]; dst = ei[(size_t)E + warp]; }
    else          { src = dst = warp - E; }

    const float4* xl4 = (const float4*)(xl + (size_t)src * D2);
    const float4* xr4 = (const float4*)(xr + (size_t)dst * D2);
    const float4* at4 = (const float4*)att;

    float acc[HEADS];
#pragma unroll
    for (int h = 0; h < HEADS; h++) {
        float4 a = xl4[h * 32 + lane];
        float4 b = xr4[h * 32 + lane];
        float4 w = at4[h * 32 + lane];
        float vx = a.x + b.x; vx = vx > 0.f ? vx : NEG * vx;
        float vy = a.y + b.y; vy = vy > 0.f ? vy : NEG * vy;
        float vz = a.z + b.z; vz = vz > 0.f ? vz : NEG * vz;
        float vw = a.w + b.w; vw = vw > 0.f ? vw : NEG * vw;
        acc[h] = vx * w.x + vy * w.y + vz * w.z + vw * w.w;
    }
#pragma unroll
    for (int off = 16; off > 0; off >>= 1)
#pragma unroll
        for (int h = 0; h < HEADS; h++)
            acc[h] += __shfl_xor_sync(0xffffffffu, acc[h], off);

    if (lane == 0) {
#pragma unroll
        for (int h = 0; h < HEADS; h++) {
            float pv = __expf(acc[h]);
            p[(size_t)warp * HEADS + h] = pv;
            atomicAdd(denom + (size_t)dst * HEADS + h, pv);
        }
    }
}

// ---------------- edge pass B: out[dst] += alpha * xl[src] ----------------
__global__ void edge_aggregate_kernel(const float* __restrict__ xl,
                                      const float* __restrict__ p,
                                      const float* __restrict__ denom,
                                      const int* __restrict__ ei,
                                      int E, int ET,
                                      float* __restrict__ out)
{
    int warp = (blockIdx.x * blockDim.x + threadIdx.x) >> 5;
    int lane = threadIdx.x & 31;
    if (warp >= ET) return;

    int src, dst;
    if (warp < E) { src = ei[warp]; dst = ei[(size_t)E + warp]; }
    else          { src = dst = warp - E; }

    float av = 0.f;
    if (lane < HEADS)
        av = p[(size_t)warp * HEADS + lane] / denom[(size_t)dst * HEADS + lane];
    float al[HEADS];
#pragma unroll
    for (int h = 0; h < HEADS; h++)
        al[h] = __shfl_sync(0xffffffffu, av, h);

    const float4* xl4 = (const float4*)(xl + (size_t)src * D2);
    float4*       o4  = (float4*)(out + (size_t)dst * D2);
#pragma unroll
    for (int h = 0; h < HEADS; h++) {
        float4 v = xl4[h * 32 + lane];
        float  a = al[h];
        float4* addr = o4 + h * 32 + lane;
        asm volatile("red.global.add.v4.f32 [%0], {%1, %2, %3, %4};"
                     :: "l"(addr), "f"(v.x * a), "f"(v.y * a),
                        "f"(v.z * a), "f"(v.w * a)
                     : "memory");
    }
}

// ---------------- elementwise: buf = elu(buf + bias) ----------------------
__global__ void elu_bias_kernel(float* __restrict__ buf,
                                const float* __restrict__ bias, int n)
{
    int i = blockIdx.x * blockDim.x + threadIdx.x;
    if (i < n) {
        float v = buf[i] + bias[i & (D2 - 1)];
        buf[i] = v > 0.f ? v : expm1f(v);
    }
}

// ---------------- host orchestration --------------------------------------
static void run_layer(const float* act, int K,
                      const float* Wl, const float* Wr,
                      const float* att, const float* bias,
                      const int* ei, int E, int ET,
                      float* xl, float* xr, float* p, float* den,
                      float* outbuf)
{
    dim3 gg((D2 + 127) / 128, (N_NODES + 127) / 128);
    sgemm_kernel<<<gg, 256>>>(act, Wl, xl, N_NODES, D2, K, nullptr);
    sgemm_kernel<<<gg, 256>>>(act, Wr, xr, N_NODES, D2, K, nullptr);

    cudaMemsetAsync(den, 0, (size_t)N_NODES * HEADS * sizeof(float));
    int eb = (ET * 32 + 255) / 256;
    edge_logits_kernel<<<eb, 256>>>(xl, xr, ei, E, ET, att, p, den);

    cudaMemsetAsync(outbuf, 0, (size_t)N_NODES * D2 * sizeof(float));
    edge_aggregate_kernel<<<eb, 256>>>(xl, p, den, ei, E, ET, outbuf);

    int n = N_NODES * D2;
    elu_bias_kernel<<<(n + 255) / 256, 256>>>(outbuf, bias, n);
}

extern "C" void kernel_launch(void* const* d_in, const int* in_sizes, int n_in,
                              void* d_out, int out_size)
{
    const float* x    = (const float*)d_in[0];
    const int*   ei   = (const int*)d_in[1];   // JAX default x64-disabled => int32
    const float* W1l  = (const float*)d_in[2];
    const float* W1r  = (const float*)d_in[3];
    const float* att1 = (const float*)d_in[4];
    const float* b1   = (const float*)d_in[5];
    const float* W2l  = (const float*)d_in[6];
    const float* W2r  = (const float*)d_in[7];
    const float* att2 = (const float*)d_in[8];
    const float* b2   = (const float*)d_in[9];
    const float* Wc   = (const float*)d_in[10];
    const float* bc   = (const float*)d_in[11];

    const int E    = in_sizes[1] / 2;          // 400000
    const int ET   = E + N_NODES;              // + self loops
    const int K_in = in_sizes[0] / N_NODES;    // 55

    float *bufA, *bufB, *xl, *xr, *p, *den;
    cudaGetSymbolAddress((void**)&bufA, g_bufA);
    cudaGetSymbolAddress((void**)&bufB, g_bufB);
    cudaGetSymbolAddress((void**)&xl,   g_xl);
    cudaGetSymbolAddress((void**)&xr,   g_xr);
    cudaGetSymbolAddress((void**)&p,    g_p);
    cudaGetSymbolAddress((void**)&den,  g_den);

    // layer 1: x -> bufB
    run_layer(x, K_in, W1l, W1r, att1, b1, ei, E, ET, xl, xr, p, den, bufB);
    // layer 2: bufB -> bufA
    run_layer(bufB, D2, W2l, W2r, att2, b2, ei, E, ET, xl, xr, p, den, bufA);
    // layer 3 (conv2 applied again): bufA -> bufB
    run_layer(bufA, D2, W2l, W2r, att2, b2, ei, E, ET, xl, xr, p, den, bufB);

    // classifier: d_out = bufB @ Wc + bc   (N = 49)
    dim3 gc((49 + 127) / 128, (N_NODES + 127) / 128);
    sgemm_kernel<<<gc, 256>>>(bufB, Wc, (float*)d_out, N_NODES, 49, D2, bc);
}

// round 4
// speedup vs baseline: 1.0044x; 1.0044x over previous
#include <cuda_runtime.h>
#include <math.h>
#include <stdint.h>

#define N_NODES 50000
#define D2      512
#define HEADS   4
#define CH      128
#define NEG     0.2f
#define MAXE    450048   // 400000 edges + 50000 self loops, padded

// ---------------- scratch (static device globals; no runtime alloc) -------
__device__ __align__(128) float g_bufA[(size_t)N_NODES * D2];
__device__ __align__(128) float g_bufB[(size_t)N_NODES * D2];
__device__ __align__(128) float g_xl  [(size_t)N_NODES * D2];
__device__ __align__(128) float g_xr  [(size_t)N_NODES * D2];
__device__ __align__(128) float g_p   [(size_t)MAXE * HEADS];
__device__ __align__(128) float g_den [(size_t)N_NODES * HEADS];

// ---------------- fp32 tiled SGEMM: C[M,N] = A[M,K] @ B[K,N] (+bias) ------
// 128x128 tile, BK=16, 256 threads, 8x8 per thread.
__global__ void __launch_bounds__(256)
sgemm_kernel(const float* __restrict__ A, const float* __restrict__ B,
             float* __restrict__ C, int M, int N, int K,
             const float* __restrict__ bias)
{
    __shared__ float As[16][128];
    __shared__ float Bs[16][128];

    const int tid  = threadIdx.x;
    const int tx   = tid & 15;
    const int ty   = tid >> 4;
    const int row0 = blockIdx.y * 128;
    const int col0 = blockIdx.x * 128;

    float acc[8][8];
#pragma unroll
    for (int i = 0; i < 8; i++)
#pragma unroll
        for (int j = 0; j < 8; j++) acc[i][j] = 0.f;

    const int a_r = tid >> 1;          // 0..127
    const int a_c = (tid & 1) * 8;     // 0 or 8
    const int b_r = tid >> 5;          // 0..7
    const int b_c = (tid & 31) * 4;    // 0..124

    for (int k0 = 0; k0 < K; k0 += 16) {
        // A tile (transposed into As[k][m])
#pragma unroll
        for (int i = 0; i < 8; i++) {
            int kk = k0 + a_c + i;
            float v = 0.f;
            if (row0 + a_r < M && kk < K)
                v = A[(size_t)(row0 + a_r) * K + kk];
            As[a_c + i][a_r] = v;
        }
        // B tile
#pragma unroll
        for (int i = 0; i < 2; i++) {
            int kk = k0 + b_r + i * 8;
#pragma unroll
            for (int j = 0; j < 4; j++) {
                int cc = col0 + b_c + j;
                float v = 0.f;
                if (kk < K && cc < N)
                    v = B[(size_t)kk * N + cc];
                Bs[b_r + i * 8][b_c + j] = v;
            }
        }
        __syncthreads();

#pragma unroll
        for (int kk = 0; kk < 16; kk++) {
            float a[8], b[8];
#pragma unroll
            for (int i = 0; i < 4; i++) {
                a[i]     = As[kk][ty * 4 + i];
                a[4 + i] = As[kk][64 + ty * 4 + i];
            }
#pragma unroll
            for (int j = 0; j < 4; j++) {
                b[j]     = Bs[kk][tx * 4 + j];
                b[4 + j] = Bs[kk][64 + tx * 4 + j];
            }
#pragma unroll
            for (int i = 0; i < 8; i++)
#pragma unroll
                for (int j = 0; j < 8; j++)
                    acc[i][j] = fmaf(a[i], b[j], acc[i][j]);
        }
        __syncthreads();
    }

#pragma unroll
    for (int i = 0; i < 8; i++) {
        int r = row0 + ((i < 4) ? (ty * 4 + i) : (64 + ty * 4 + (i - 4)));
        if (r >= M) continue;
#pragma unroll
        for (int j = 0; j < 8; j++) {
            int c = col0 + ((j < 4) ? (tx * 4 + j) : (64 + tx * 4 + (j - 4)));
            if (c < N)
                C[(size_t)r * N + c] = acc[i][j] + (bias ? bias[c] : 0.f);
        }
    }
}

// ---------------- edge pass A: logits -> p = exp(logit), denom += p -------
// One warp per edge (edges >= E are implicit self loops).
// Softmax is shift-invariant: skipping the segment-max pass is exact as long
// as exp() doesn't overflow; logits here are O(1).
__global__ void edge_logits_kernel(const float* __restrict__ xl,
                                   const float* __restrict__ xr,
                                   const int* __restrict__ ei,
                                   int E, int ET,
                                   const float* __restrict__ att,
                                   float* __restrict__ p,
                                   float* __restrict__ denom)
{
    int warp = (blockIdx.x * blockDim.x + threadIdx.x) >> 5;
    int lane = threadIdx.x & 31;
    if (warp >= ET) return;

    int src, dst;
    if (warp < E) { src = ei[warp]; dst = ei[(size_t)E + warp]; }
    else          { src = dst = warp - E; }

    const float4* xl4 = (const float4*)(xl + (size_t)src * D2);
    const float4* xr4 = (const float4*)(xr + (size_t)dst * D2);
    const float4* at4 = (const float4*)att;

    float acc[HEADS];
#pragma unroll
    for (int h = 0; h < HEADS; h++) {
        float4 a = xl4[h * 32 + lane];
        float4 b = xr4[h * 32 + lane];
        float4 w = at4[h * 32 + lane];
        float vx = a.x + b.x; vx = vx > 0.f ? vx : NEG * vx;
        float vy = a.y + b.y; vy = vy > 0.f ? vy : NEG * vy;
        float vz = a.z + b.z; vz = vz > 0.f ? vz : NEG * vz;
        float vw = a.w + b.w; vw = vw > 0.f ? vw : NEG * vw;
        acc[h] = vx * w.x + vy * w.y + vz * w.z + vw * w.w;
    }
#pragma unroll
    for (int off = 16; off > 0; off >>= 1)
#pragma unroll
        for (int h = 0; h < HEADS; h++)
            acc[h] += __shfl_xor_sync(0xffffffffu, acc[h], off);

    if (lane == 0) {
#pragma unroll
        for (int h = 0; h < HEADS; h++) {
            float pv = __expf(acc[h]);
            p[(size_t)warp * HEADS + h] = pv;
            atomicAdd(denom + (size_t)dst * HEADS + h, pv);
        }
    }
}

// ---------------- edge pass B: out[dst] += alpha * xl[src] ----------------
__global__ void edge_aggregate_kernel(const float* __restrict__ xl,
                                      const float* __restrict__ p,
                                      const float* __restrict__ denom,
                                      const int* __restrict__ ei,
                                      int E, int ET,
                                      float* __restrict__ out)
{
    int warp = (blockIdx.x * blockDim.x + threadIdx.x) >> 5;
    int lane = threadIdx.x & 31;
    if (warp >= ET) return;

    int src, dst;
    if (warp < E) { src = ei[warp]; dst = ei[(size_t)E + warp]; }
    else          { src = dst = warp - E; }

    float av = 0.f;
    if (lane < HEADS)
        av = p[(size_t)warp * HEADS + lane] / denom[(size_t)dst * HEADS + lane];
    float al[HEADS];
#pragma unroll
    for (int h = 0; h < HEADS; h++)
        al[h] = __shfl_sync(0xffffffffu, av, h);

    const float4* xl4 = (const float4*)(xl + (size_t)src * D2);
    float4*       o4  = (float4*)(out + (size_t)dst * D2);
#pragma unroll
    for (int h = 0; h < HEADS; h++) {
        float4 v = xl4[h * 32 + lane];
        float  a = al[h];
        float4* addr = o4 + h * 32 + lane;
        asm volatile("red.global.add.v4.f32 [%0], {%1, %2, %3, %4};"
                     :: "l"(addr), "f"(v.x * a), "f"(v.y * a),
                        "f"(v.z * a), "f"(v.w * a)
                     : "memory");
    }
}

// ---------------- elementwise: buf = elu(buf + bias) ----------------------
__global__ void elu_bias_kernel(float* __restrict__ buf,
                                const float* __restrict__ bias, int n)
{
    int i = blockIdx.x * blockDim.x + threadIdx.x;
    if (i < n) {
        float v = buf[i] + bias[i & (D2 - 1)];
        buf[i] = v > 0.f ? v : expm1f(v);
    }
}

// ---------------- host orchestration --------------------------------------
static void run_layer(const float* act, int K,
                      const float* Wl, const float* Wr,
                      const float* att, const float* bias,
                      const int* ei, int E, int ET,
                      float* xl, float* xr, float* p, float* den,
                      float* outbuf)
{
    dim3 gg((D2 + 127) / 128, (N_NODES + 127) / 128);
    sgemm_kernel<<<gg, 256>>>(act, Wl, xl, N_NODES, D2, K, nullptr);
    sgemm_kernel<<<gg, 256>>>(act, Wr, xr, N_NODES, D2, K, nullptr);

    cudaMemsetAsync(den, 0, (size_t)N_NODES * HEADS * sizeof(float));
    int eb = (ET * 32 + 255) / 256;
    edge_logits_kernel<<<eb, 256>>>(xl, xr, ei, E, ET, att, p, den);

    cudaMemsetAsync(outbuf, 0, (size_t)N_NODES * D2 * sizeof(float));
    edge_aggregate_kernel<<<eb, 256>>>(xl, p, den, ei, E, ET, outbuf);

    int n = N_NODES * D2;
    elu_bias_kernel<<<(n + 255) / 256, 256>>>(outbuf, bias, n);
}

extern "C" void kernel_launch(void* const* d_in, const int* in_sizes, int n_in,
                              void* d_out, int out_size)
{
    const float* x    = (const float*)d_in[0];
    const int*   ei   = (const int*)d_in[1];   // JAX default x64-disabled => int32
    const float* W1l  = (const float*)d_in[2];
    const float* W1r  = (const float*)d_in[3];
    const float* att1 = (const float*)d_in[4];
    const float* b1   = (const float*)d_in[5];
    const float* W2l  = (const float*)d_in[6];
    const float* W2r  = (const float*)d_in[7];
    const float* att2 = (const float*)d_in[8];
    const float* b2   = (const float*)d_in[9];
    const float* Wc   = (const float*)d_in[10];
    const float* bc   = (const float*)d_in[11];

    const int E    = in_sizes[1] / 2;          // 400000
    const int ET   = E + N_NODES;              // + self loops
    const int K_in = in_sizes[0] / N_NODES;    // 55

    float *bufA, *bufB, *xl, *xr, *p, *den;
    cudaGetSymbolAddress((void**)&bufA, g_bufA);
    cudaGetSymbolAddress((void**)&bufB, g_bufB);
    cudaGetSymbolAddress((void**)&xl,   g_xl);
    cudaGetSymbolAddress((void**)&xr,   g_xr);
    cudaGetSymbolAddress((void**)&p,    g_p);
    cudaGetSymbolAddress((void**)&den,  g_den);

    // layer 1: x -> bufB
    run_layer(x, K_in, W1l, W1r, att1, b1, ei, E, ET, xl, xr, p, den, bufB);
    // layer 2: bufB -> bufA
    run_layer(bufB, D2, W2l, W2r, att2, b2, ei, E, ET, xl, xr, p, den, bufA);
    // layer 3 (conv2 applied again): bufA -> bufB
    run_layer(bufA, D2, W2l, W2r, att2, b2, ei, E, ET, xl, xr, p, den, bufB);

    // classifier: d_out = bufB @ Wc + bc   (N = 49)
    dim3 gc((49 + 127) / 128, (N_NODES + 127) / 128);
    sgemm_kernel<<<gc, 256>>>(bufB, Wc, (float*)d_out, N_NODES, 49, D2, bc);
}